// round 7
// baseline (speedup 1.0000x reference)
#include <cuda_runtime.h>
#include <cuda_fp16.h>
#include <cuda_bf16.h>
#include <cstdint>

// MeanAggregator: out[i,:] = mean_{e<EPN} features[edge_dst[i*EPN+e], :], D=128.
// R7: fp32 gather is pinned at ~15.2 TB/s regardless of LDG granularity/MLP
// (R1/R3/R6 all ~28.5us). Only byte reduction moved time (fp16 gather 20.7us).
// Two-kernel fp16 path, both halves tuned:
//  - convert: 1 float4/thread single-shot, __ldcs (evict-first) fp32 reads so the
//    read-once table doesn't evict the hot fp16 cache from L2.
//  - gather: TWO nodes per warp (34 independent LDG.64 in flight), __stcs output.

#define D_DIM 128
#define N_CAP 100000          // capacity of the fp16 scratch table (rows)

// fp16 feature cache: N_CAP * 128 halves = 25.6 MB. uint2 = 4 halves = 8B.
__device__ uint2 g_feat16[(size_t)N_CAP * (D_DIM / 4)];

// ---------------- conversion: fp32 table -> fp16 scratch ----------------
__global__ __launch_bounds__(256) void convert_f32_to_f16(
    const float* __restrict__ feat, int n4)   // n4 = total floats / 4
{
    const int i = blockIdx.x * blockDim.x + threadIdx.x;
    if (i >= n4) return;
    // Streaming (evict-first) read: fp32 table is read once per launch.
    const float4 f = __ldcs(reinterpret_cast<const float4*>(feat) + i);
    const __half2 h0 = __floats2half2_rn(f.x, f.y);
    const __half2 h1 = __floats2half2_rn(f.z, f.w);
    uint2 u;
    u.x = *reinterpret_cast<const uint32_t*>(&h0);
    u.y = *reinterpret_cast<const uint32_t*>(&h1);
    g_feat16[i] = u;
}

// ---------------- gather from fp16 cache, 2 nodes per warp ----------------
// Lane l owns columns [4l,4l+4) (one uint2 per row). Warp w handles nodes
// 2w and 2w+1 -> up to 2*EPN independent gathers in the scheduling window.
template <int EPN>
__global__ __launch_bounds__(256) void mean_agg_f16_2n(
    const int* __restrict__ edge_dst,
    float*     __restrict__ out,
    int B)
{
    const int warp = (blockIdx.x * blockDim.x + threadIdx.x) >> 5;
    const int lane = threadIdx.x & 31;
    const int n0 = warp * 2;
    if (n0 >= B) return;
    const bool has2 = (n0 + 1 < B);

    static_assert(2 * EPN <= 64, "index staging needs 2*EPN <= 64");

    // Stage up to 2*EPN indices across the warp (two coalesced loads).
    const int* __restrict__ idx = edge_dst + (size_t)n0 * EPN;
    const int nvalid = has2 ? 2 * EPN : EPN;
    int ia = 0, ib = 0;
    if (lane < nvalid) ia = __ldg(idx + lane);                     // 0..31
    if (nvalid > 32 && lane < nvalid - 32) ib = __ldg(idx + 32 + lane); // 32..

    float4 accA = make_float4(0.f, 0.f, 0.f, 0.f);
    float4 accB = make_float4(0.f, 0.f, 0.f, 0.f);

#pragma unroll
    for (int e = 0; e < EPN; ++e) {
        const int nbA = __shfl_sync(0xFFFFFFFFu, ia, e);
        const int eB  = e + EPN;
        const int nbB = (eB < 32) ? __shfl_sync(0xFFFFFFFFu, ia, eB)
                                  : __shfl_sync(0xFFFFFFFFu, ib, eB - 32);

        const uint2 uA = __ldg(g_feat16 + (size_t)nbA * (D_DIM / 4) + lane);
        uint2 uB = make_uint2(0u, 0u);
        if (has2) uB = __ldg(g_feat16 + (size_t)nbB * (D_DIM / 4) + lane);

        {
            const __half2 h0 = *reinterpret_cast<const __half2*>(&uA.x);
            const __half2 h1 = *reinterpret_cast<const __half2*>(&uA.y);
            const float2 a = __half22float2(h0);
            const float2 b = __half22float2(h1);
            accA.x += a.x; accA.y += a.y; accA.z += b.x; accA.w += b.y;
        }
        if (has2) {
            const __half2 h0 = *reinterpret_cast<const __half2*>(&uB.x);
            const __half2 h1 = *reinterpret_cast<const __half2*>(&uB.y);
            const float2 a = __half22float2(h0);
            const float2 b = __half22float2(h1);
            accB.x += a.x; accB.y += a.y; accB.z += b.x; accB.w += b.y;
        }
    }

    const float inv = 1.0f / (float)EPN;
    accA.x *= inv; accA.y *= inv; accA.z *= inv; accA.w *= inv;
    // Streaming stores: output is write-once; keep L2 for the fp16 table.
    __stcs(reinterpret_cast<float4*>(out + (size_t)n0 * D_DIM) + lane, accA);
    if (has2) {
        accB.x *= inv; accB.y *= inv; accB.z *= inv; accB.w *= inv;
        __stcs(reinterpret_cast<float4*>(out + (size_t)(n0 + 1) * D_DIM) + lane, accB);
    }
}

// ---------------- fp32 fallback (proven R1 path) ----------------
__global__ __launch_bounds__(256) void mean_agg_f32_dyn(
    const float* __restrict__ feat,
    const int*   __restrict__ edge_dst,
    float*       __restrict__ out,
    int B, int epn)
{
    const int warp = (blockIdx.x * blockDim.x + threadIdx.x) >> 5;
    const int lane = threadIdx.x & 31;
    if (warp >= B) return;

    const int* __restrict__ idx = edge_dst + (size_t)warp * epn;
    float4 acc = make_float4(0.f, 0.f, 0.f, 0.f);
#pragma unroll 4
    for (int e = 0; e < epn; ++e) {
        const int nb = __ldg(idx + e);
        const float4 v = __ldg(reinterpret_cast<const float4*>(
                                   feat + (size_t)nb * D_DIM) + lane);
        acc.x += v.x; acc.y += v.y; acc.z += v.z; acc.w += v.w;
    }
    const float inv = 1.0f / (float)epn;
    acc.x *= inv; acc.y *= inv; acc.z *= inv; acc.w *= inv;
    reinterpret_cast<float4*>(out + (size_t)warp * D_DIM)[lane] = acc;
}

extern "C" void kernel_launch(void* const* d_in, const int* in_sizes, int n_in,
                              void* d_out, int out_size)
{
    const float* feat     = (const float*)d_in[0];
    const int*   edge_dst = (const int*)d_in[2];
    float*       out      = (float*)d_out;

    const int B       = out_size / D_DIM;      // 50000
    const int E       = in_sizes[2];           // 850000
    const int epn     = E / B;                 // 17
    const int n_feat  = in_sizes[0];           // N_TOTAL * D
    const int n_rows  = n_feat / D_DIM;        // 100000

    const int threads = 256;

    if (epn == 17 && n_rows <= N_CAP && n_feat % 4 == 0) {
        const int n4 = n_feat / 4;             // 3.2M float4s
        convert_f32_to_f16<<<(n4 + threads - 1) / threads, threads>>>(feat, n4);
        const int nwarps  = (B + 1) / 2;       // 2 nodes per warp
        const int blocks  = (nwarps * 32 + threads - 1) / threads;
        mean_agg_f16_2n<17><<<blocks, threads>>>(edge_dst, out, B);
    } else {
        const int blocks = (B * 32 + threads - 1) / threads;
        mean_agg_f32_dyn<<<blocks, threads>>>(feat, edge_dst, out, B, epn);
    }
}

// round 8
// speedup vs baseline: 1.0689x; 1.0689x over previous
#include <cuda_runtime.h>
#include <cuda_bf16.h>
#include <cstdint>

// MeanAggregator: out[i,:] = mean_{e<EPN} features[edge_dst[i*EPN+e], :], D=128 f32.
// R8: gather is capped by a per-SM outstanding-SECTOR limit (~450) on the LDG
// register-return path (retrodicts R1/R6/R7 at ~15.3 TB/s regardless of LDG
// width/MLP). cp.async (LDGSTS) completes into smem via a separate path with
// no observed depth cap -> split each node's 17 rows: 9 LDG.128 (register
// path) + 8 cp.async.cg 16B/lane (smem path). Each lane reads back only its
// own 16B slice -> per-thread wait_group, no warp sync needed.

#define D_DIM   128
#define EPN     17
#define CP_ROWS 8              // rows fetched via cp.async
#define LDG_ROWS (EPN - CP_ROWS) // 9 rows via LDG.128
#define WARPS_PER_CTA 8

__device__ __forceinline__ uint32_t smem_u32(const void* p) {
    return (uint32_t)__cvta_generic_to_shared(p);
}

__global__ __launch_bounds__(32 * WARPS_PER_CTA) void mean_agg_hybrid(
    const float* __restrict__ feat,
    const int*   __restrict__ edge_dst,
    float*       __restrict__ out,
    int B)
{
    // 8 warps x 8 rows x 32 lanes x 16B = 32 KB static smem.
    __shared__ float4 tile[WARPS_PER_CTA][CP_ROWS][32];

    const int warp  = (blockIdx.x * blockDim.x + threadIdx.x) >> 5;
    const int wloc  = (threadIdx.x >> 5);
    const int lane  = threadIdx.x & 31;
    if (warp >= B) return;

    // Stage indices: one coalesced load + shuffles.
    const int* __restrict__ idx = edge_dst + (size_t)warp * EPN;
    int myidx = 0;
    if (lane < EPN) myidx = __ldg(idx + lane);

    // ---- Phase A: 8 rows via cp.async.cg (smem path, bypasses LDG cap) ----
#pragma unroll
    for (int r = 0; r < CP_ROWS; ++r) {
        const int nb = __shfl_sync(0xFFFFFFFFu, myidx, r);
        const float4* src = reinterpret_cast<const float4*>(
                                feat + (size_t)nb * D_DIM) + lane;
        const uint32_t dst = smem_u32(&tile[wloc][r][lane]);
        asm volatile("cp.async.cg.shared.global [%0], [%1], 16;"
                     :: "r"(dst), "l"(src) : "memory");
    }
    asm volatile("cp.async.commit_group;" ::: "memory");

    // ---- Phase B: 9 rows via LDG.128 (register path, saturates its cap) ----
    float4 v[LDG_ROWS];
#pragma unroll
    for (int r = 0; r < LDG_ROWS; ++r) {
        const int nb = __shfl_sync(0xFFFFFFFFu, myidx, CP_ROWS + r);
        v[r] = __ldg(reinterpret_cast<const float4*>(
                         feat + (size_t)nb * D_DIM) + lane);
    }

    // Reduce register rows.
    float4 acc = make_float4(0.f, 0.f, 0.f, 0.f);
#pragma unroll
    for (int r = 0; r < LDG_ROWS; ++r) {
        acc.x += v[r].x; acc.y += v[r].y;
        acc.z += v[r].z; acc.w += v[r].w;
    }

    // Wait for this thread's async copies; each lane reads only its own slots.
    asm volatile("cp.async.wait_group 0;" ::: "memory");
#pragma unroll
    for (int r = 0; r < CP_ROWS; ++r) {
        const float4 s = tile[wloc][r][lane];
        acc.x += s.x; acc.y += s.y; acc.z += s.z; acc.w += s.w;
    }

    const float inv = 1.0f / (float)EPN;
    acc.x *= inv; acc.y *= inv; acc.z *= inv; acc.w *= inv;
    reinterpret_cast<float4*>(out + (size_t)warp * D_DIM)[lane] = acc;
}

// General fallback: runtime EPN (proven R6-style float2 path).
__global__ __launch_bounds__(256) void mean_agg_kernel_dyn(
    const float* __restrict__ feat,
    const int*   __restrict__ edge_dst,
    float*       __restrict__ out,
    int B, int epn)
{
    const int warp = (blockIdx.x * blockDim.x + threadIdx.x) >> 5;
    const int lane = threadIdx.x & 31;
    if (warp >= B) return;

    const int* __restrict__ idx = edge_dst + (size_t)warp * epn;
    float2 acc0 = make_float2(0.f, 0.f);
    float2 acc1 = make_float2(0.f, 0.f);
#pragma unroll 4
    for (int e = 0; e < epn; ++e) {
        const int nb = __ldg(idx + e);
        const float2* __restrict__ row =
            reinterpret_cast<const float2*>(feat + (size_t)nb * D_DIM);
        const float2 v0 = __ldg(row + lane);
        const float2 v1 = __ldg(row + 32 + lane);
        acc0.x += v0.x; acc0.y += v0.y;
        acc1.x += v1.x; acc1.y += v1.y;
    }
    const float inv = 1.0f / (float)epn;
    acc0.x *= inv; acc0.y *= inv;
    acc1.x *= inv; acc1.y *= inv;
    float2* __restrict__ orow =
        reinterpret_cast<float2*>(out + (size_t)warp * D_DIM);
    orow[lane]      = acc0;
    orow[32 + lane] = acc1;
}

extern "C" void kernel_launch(void* const* d_in, const int* in_sizes, int n_in,
                              void* d_out, int out_size)
{
    const float* feat     = (const float*)d_in[0];
    const int*   edge_dst = (const int*)d_in[2];
    float*       out      = (float*)d_out;

    const int B   = out_size / D_DIM;   // 50000
    const int E   = in_sizes[2];        // 850000
    const int epn = E / B;              // 17

    const int threads = 32 * WARPS_PER_CTA;   // 256
    const int blocks  = (B * 32 + threads - 1) / threads;

    if (epn == EPN) {
        mean_agg_hybrid<<<blocks, threads>>>(feat, edge_dst, out, B);
    } else {
        mean_agg_kernel_dyn<<<blocks, threads>>>(feat, edge_dst, out, B, epn);
    }
}